// round 7
// baseline (speedup 1.0000x reference)
#include <cuda_runtime.h>
#include <cuda_fp16.h>

#define NB 128
#define NB3 (NB * NB * NB)

// y-pair table: P[ix][iy][iz] = { G(ix,iy,iz) 4xfp16, G(ix,min(iy+1,127),iz) 4xfp16 }
// 16 B/entry, 33.5 MB -> L2-resident. z-neighbors are ADJACENT entries, so a
// lane pair covering (iz0, iz0+1) hits one 128B line per instruction.
__device__ uint4 g_ypairs[NB3];

__device__ __forceinline__ uint2 pack_h4(float4 v)
{
    __half2 h0 = __floats2half2_rn(v.x, v.y);
    __half2 h1 = __floats2half2_rn(v.z, v.w);
    uint2 r;
    r.x = *reinterpret_cast<const unsigned int*>(&h0);
    r.y = *reinterpret_cast<const unsigned int*>(&h1);
    return r;
}

__global__ __launch_bounds__(256)
void build_ypairs_kernel(const float4* __restrict__ grid)
{
    int idx = blockIdx.x * blockDim.x + threadIdx.x;
    if (idx >= NB3) return;

    int iy = (idx >> 7) & (NB - 1);
    int dy = (iy < NB - 1) ? NB : 0;

    float4 a = grid[idx];        // (ix, iy,   iz)
    float4 b = grid[idx + dy];   // (ix, iy+1, iz) clamped

    uint2 pa = pack_h4(a);
    uint2 pb = pack_h4(b);

    uint4 v;
    v.x = pa.x; v.y = pa.y; v.z = pb.x; v.w = pb.y;
    g_ypairs[idx] = v;
}

// y-lerp of one entry: corner_y0*wy0 + corner_y1*wy1
__device__ __forceinline__ float4 ylerp(uint4 p, float wy0, float wy1)
{
    float2 axy = __half22float2(*reinterpret_cast<const __half2*>(&p.x));
    float2 azw = __half22float2(*reinterpret_cast<const __half2*>(&p.y));
    float2 bxy = __half22float2(*reinterpret_cast<const __half2*>(&p.z));
    float2 bzw = __half22float2(*reinterpret_cast<const __half2*>(&p.w));

    float4 r;
    r.x = fmaf(wy1, bxy.x, wy0 * axy.x);
    r.y = fmaf(wy1, bxy.y, wy0 * axy.y);
    r.z = fmaf(wy1, bzw.x, wy0 * azw.x);
    r.w = fmaf(wy1, bzw.y, wy0 * azw.y);
    return r;
}

struct Setup {
    int e0, e1;        // table entries for this lane's z-slice (x0, x1 cells)
    float fx, fy, wz;  // wz = this lane's z weight
};

__device__ __forceinline__ Setup make_setup(float px, float py, float pz, int q)
{
    px = fminf(fmaxf(px * (float)NB, 0.0f), (float)(NB - 1));
    py = fminf(fmaxf(py * (float)NB, 0.0f), (float)(NB - 1));
    pz = fminf(fmaxf(pz * (float)NB, 0.0f), (float)(NB - 1));

    int ix0 = (int)floorf(px);
    int iy0 = (int)floorf(py);
    int iz0 = (int)floorf(pz);

    Setup s;
    s.fx = px - (float)ix0;
    s.fy = py - (float)iy0;
    float fz = pz - (float)iz0;
    s.wz = q ? fz : (1.0f - fz);

    int ix1 = min(ix0 + 1, NB - 1);
    int izq = min(iz0 + q, NB - 1);

    s.e0 = (ix0 * NB + iy0) * NB + izq;
    s.e1 = (ix1 * NB + iy0) * NB + izq;
    return s;
}

// Partial result for this lane's z-slice (all 4 channels, weighted by wz).
__device__ __forceinline__ float4 lane_partial(uint4 A, uint4 B, const Setup& s)
{
    float wy1 = s.fy, wy0 = 1.0f - s.fy;
    float4 m0 = ylerp(A, wy0, wy1);
    float4 m1 = ylerp(B, wy0, wy1);

    float wx1 = s.fx, wx0 = 1.0f - s.fx;
    float4 r;
    r.x = s.wz * fmaf(wx1, m1.x, wx0 * m0.x);
    r.y = s.wz * fmaf(wx1, m1.y, wx0 * m0.y);
    r.z = s.wz * fmaf(wx1, m1.z, wx0 * m0.z);
    r.w = s.wz * fmaf(wx1, m1.w, wx0 * m0.w);
    return r;
}

// Half-exchange: lane0 finalizes {x,y}, lane1 finalizes {z,w}; 2 shfls/point.
__device__ __forceinline__ float2 reduce_half(float4 r, int q)
{
    float s1 = __shfl_xor_sync(0xFFFFFFFFu, q ? r.x : r.z, 1);
    float s2 = __shfl_xor_sync(0xFFFFFFFFu, q ? r.y : r.w, 1);
    float2 o;
    if (q == 0) { o.x = r.x + s1; o.y = r.y + s2; }
    else        { o.x = r.z + s1; o.y = r.w + s2; }
    return o;
}

// 2 lanes per point, 4 points per lane-pair -> 8 gathers in flight per thread.
// __launch_bounds__(256, 4): cap 1024 thr/SM -> 64 regs available, no forced squeeze.
__global__ __launch_bounds__(256, 4)
void interp_coop4_kernel(const float* __restrict__ x,
                         float2* __restrict__ out,   // [N,4] viewed as float2[2N]
                         int n, int h)
{
    int tid = blockIdx.x * blockDim.x + threadIdx.x;
    int p0  = tid >> 1;
    int q   = tid & 1;

    if (p0 >= h) return;
    int p1 = p0 + h;
    int p2 = p0 + 2 * h;
    int p3 = p0 + 3 * h;
    bool v1 = (p1 < n), v2 = (p2 < n), v3 = (p3 < n);
    int c1 = v1 ? p1 : p0;
    int c2 = v2 ? p2 : p0;
    int c3 = v3 ? p3 : p0;

    Setup S0 = make_setup(x[3 * p0 + 0], x[3 * p0 + 1], x[3 * p0 + 2], q);
    Setup S1 = make_setup(x[3 * c1 + 0], x[3 * c1 + 1], x[3 * c1 + 2], q);
    Setup S2 = make_setup(x[3 * c2 + 0], x[3 * c2 + 1], x[3 * c2 + 2], q);
    Setup S3 = make_setup(x[3 * c3 + 0], x[3 * c3 + 1], x[3 * c3 + 2], q);

    // 8 gathers back-to-back; each lane-pair touches 1 distinct line per instr.
    uint4 A0 = __ldg(&g_ypairs[S0.e0]);
    uint4 B0 = __ldg(&g_ypairs[S0.e1]);
    uint4 A1 = __ldg(&g_ypairs[S1.e0]);
    uint4 B1 = __ldg(&g_ypairs[S1.e1]);
    uint4 A2 = __ldg(&g_ypairs[S2.e0]);
    uint4 B2 = __ldg(&g_ypairs[S2.e1]);
    uint4 A3 = __ldg(&g_ypairs[S3.e0]);
    uint4 B3 = __ldg(&g_ypairs[S3.e1]);

    float2 o0 = reduce_half(lane_partial(A0, B0, S0), q);
    out[2 * p0 + q] = o0;

    float2 o1 = reduce_half(lane_partial(A1, B1, S1), q);
    if (v1) out[2 * p1 + q] = o1;

    float2 o2 = reduce_half(lane_partial(A2, B2, S2), q);
    if (v2) out[2 * p2 + q] = o2;

    float2 o3 = reduce_half(lane_partial(A3, B3, S3), q);
    if (v3) out[2 * p3 + q] = o3;
}

extern "C" void kernel_launch(void* const* d_in, const int* in_sizes, int n_in,
                              void* d_out, int out_size)
{
    const float*  x    = (const float*)d_in[0];   // [N,3] float32
    const float4* grid = (const float4*)d_in[1];  // [128,128,128,4] float32
    float2*       out  = (float2*)d_out;          // [N,4] float32

    int n = in_sizes[0] / 3;
    int h = (n + 3) / 4;

    const int block = 256;
    build_ypairs_kernel<<<(NB3 + block - 1) / block, block>>>(grid);

    long long threads = 2LL * h;
    int grid_dim = (int)((threads + block - 1) / block);
    interp_coop4_kernel<<<grid_dim, block>>>(x, out, n, h);
}